// round 5
// baseline (speedup 1.0000x reference)
#include <cuda_runtime.h>
#include <cstdint>

#define NB 4
#define NS 8192
#define ND 512
#define NP 32
#define NT (NP + NS)          // 8224
#define LN_EPS 1e-5f
#define ZCH 128               // chunks over S for reduce
#define CROWS (NS / ZCH)      // 64 rows per chunk
#define KZ 8                  // split-K factor for GEMVs
#define KS (ND / KZ)          // 64 k per split
#define BROWS 16              // rows per TMA bulk store (16 * 2KB = 32KB)
#define NCHUNK (NT / BROWS)   // 514 chunks per batch
#define BGX 128               // bcast grid.x

// Scratch: device globals, referenced ONLY from device code.
__device__ float g_part[ZCH][NB * ND];   // per-chunk partial sums of x
__device__ float g_vp[KZ][NB * ND];      // split-K partials of vbar
__device__ float g_yp[KZ][NB * ND];      // split-K partials of y
__device__ int   g_cnt[NB];              // per-batch arrival counter (gemv1)

__device__ __forceinline__ uint32_t smem_u32(const void* p) {
    uint32_t a;
    asm("{ .reg .u64 t; cvta.to.shared.u64 t, %1; cvt.u32.u64 %0, t; }"
        : "=r"(a) : "l"(p));
    return a;
}

// ---------------------------------------------------------------------------
// K1: reduce x over S. grid (NB, ZCH), block 128. float4 loads, 64 rows/thr,
// 8 independent accumulators. Also resets the per-batch sync counters.
// ---------------------------------------------------------------------------
__global__ void reduce_x_kernel(const float4* __restrict__ x4) {
    const int d4 = threadIdx.x;            // 0..127
    const int b  = blockIdx.x;
    const int z  = blockIdx.y;
    if (z == 0 && d4 == 0) g_cnt[b] = 0;   // visible to gemv kernel at launch boundary

    const float4* p = x4 + ((size_t)(b * NS + z * CROWS)) * (ND / 4) + d4;
    float4 a[8];
#pragma unroll
    for (int j = 0; j < 8; j++) a[j] = make_float4(0.f, 0.f, 0.f, 0.f);
#pragma unroll
    for (int i = 0; i < CROWS; i += 8) {
#pragma unroll
        for (int j = 0; j < 8; j++) {
            float4 v = p[(size_t)(i + j) * (ND / 4)];
            a[j].x += v.x; a[j].y += v.y; a[j].z += v.z; a[j].w += v.w;
        }
    }
    float4 r;
    r.x = ((a[0].x + a[1].x) + (a[2].x + a[3].x)) + ((a[4].x + a[5].x) + (a[6].x + a[7].x));
    r.y = ((a[0].y + a[1].y) + (a[2].y + a[3].y)) + ((a[4].y + a[5].y) + (a[6].y + a[7].y));
    r.z = ((a[0].z + a[1].z) + (a[2].z + a[3].z)) + ((a[4].z + a[5].z) + (a[6].z + a[7].z));
    r.w = ((a[0].w + a[1].w) + (a[2].w + a[3].w)) + ((a[4].w + a[5].w) + (a[6].w + a[7].w));
    ((float4*)g_part[z])[b * (ND / 4) + d4] = r;
}

// ---------------------------------------------------------------------------
// K2: fused cbar + GEMV1 + (spin-sync) + LN + GEMV2. grid (NB, KZ), block 512.
// All 32 blocks are co-resident (<< 148 SMs), so the spin cannot deadlock.
// Summation orders are fixed -> deterministic.
// ---------------------------------------------------------------------------
__global__ void gemv_fused_kernel(const float* __restrict__ pm,
                                  const float* __restrict__ Wv,
                                  const float* __restrict__ bv,
                                  const float* __restrict__ gamma,
                                  const float* __restrict__ beta,
                                  const float* __restrict__ Wout) {
    const int b = blockIdx.x, z = blockIdx.y, d = threadIdx.x;
    __shared__ float sk[KS];
    __shared__ float red[ND];
    __shared__ float snorm[KS];

    // --- cbar slice for this split ---
    if (d < KS) {
        const int kk = z * KS + d;
        float a = 0.f;
#pragma unroll 16
        for (int c = 0; c < ZCH; c++) a += g_part[c][b * ND + kk];
#pragma unroll
        for (int p = 0; p < NP; p++) a += pm[p * ND + kk];
        sk[d] = a / (float)NT;
    }
    __syncthreads();

    // --- GEMV1 partial: vbar_z[d] = sum_{k in split} cbar[k] * Wv[k,d] ---
    {
        const float* w = Wv + (size_t)(z * KS) * ND + d;
        float acc = 0.f;
#pragma unroll
        for (int k = 0; k < KS; k++) acc += sk[k] * w[(size_t)k * ND];
        g_vp[z][b * ND + d] = acc;
    }
    __threadfence();
    __syncthreads();
    if (d == 0) atomicAdd(&g_cnt[b], 1);

    // --- wait for all 8 splits of this batch ---
    if (d == 0) {
        while (((volatile int*)g_cnt)[b] < KZ) { }
    }
    __syncthreads();
    __threadfence();

    // --- combine vbar + LayerNorm (redundant per block, identical order) ---
    float vb = bv[d];
#pragma unroll
    for (int c = 0; c < KZ; c++) vb += g_vp[c][b * ND + d];

    red[d] = vb;
    __syncthreads();
    for (int s = ND / 2; s > 0; s >>= 1) {
        if (d < s) red[d] += red[d + s];
        __syncthreads();
    }
    const float mu = red[0] / (float)ND;
    __syncthreads();
    const float diff = vb - mu;
    red[d] = diff * diff;
    __syncthreads();
    for (int s = ND / 2; s > 0; s >>= 1) {
        if (d < s) red[d] += red[d + s];
        __syncthreads();
    }
    const float inv = rsqrtf(red[0] / (float)ND + LN_EPS);
    const float nrm = diff * inv * gamma[d] + beta[d];
    if (d >= z * KS && d < (z + 1) * KS) snorm[d - z * KS] = nrm;
    __syncthreads();

    // --- GEMV2 partial ---
    const float* w = Wout + (size_t)(z * KS) * ND + d;
    float acc = 0.f;
#pragma unroll
    for (int k = 0; k < KS; k++) acc += snorm[k] * w[(size_t)k * ND];
    g_yp[z][b * ND + d] = acc;
}

// ---------------------------------------------------------------------------
// K3: combine y partials + bout, broadcast via TMA bulk stores.
// grid (BGX, NB), block 256. Each block replicates the 2KB row 16x in SMEM
// (32KB) and issues one 32KB cp.async.bulk per 16-row chunk.
// ---------------------------------------------------------------------------
__global__ void bcast_kernel(const float4* __restrict__ bout4,
                             float* __restrict__ out) {
    const int b = blockIdx.y;
    const int tid = threadIdx.x;
    __shared__ alignas(128) float4 srow[BROWS * (ND / 4)];  // 32KB

    if (tid < ND / 4) {
        float4 a = bout4[tid];
#pragma unroll
        for (int z = 0; z < KZ; z++) {
            float4 v = ((const float4*)g_yp[z])[b * (ND / 4) + tid];
            a.x += v.x; a.y += v.y; a.z += v.z; a.w += v.w;
        }
#pragma unroll
        for (int r = 0; r < BROWS; r++) srow[r * (ND / 4) + tid] = a;
    }
    __syncthreads();

    if (tid == 0) {
        const uint32_t saddr = smem_u32(srow);
        char* obase = (char*)(out + (size_t)b * NT * ND);
        for (int c = blockIdx.x; c < NCHUNK; c += BGX) {
            char* dst = obase + (size_t)c * (BROWS * ND * 4);  // 32KB chunks
            asm volatile(
                "cp.async.bulk.global.shared::cta.bulk_group [%0], [%1], %2;"
                :: "l"(dst), "r"(saddr), "r"((int)(BROWS * ND * 4)) : "memory");
        }
        asm volatile("cp.async.bulk.commit_group;" ::: "memory");
        asm volatile("cp.async.bulk.wait_group.read 0;" ::: "memory");
    }
}

// ---------------------------------------------------------------------------
extern "C" void kernel_launch(void* const* d_in, const int* in_sizes, int n_in,
                              void* d_out, int out_size) {
    const float* x     = (const float*)d_in[0];
    const float* pm    = (const float*)d_in[1];
    // d_in[2]=Wk, [3]=bk, [6]=Wq, [7]=bq unused: softmax over zero-state and
    // constant-in-m logits collapse to uniform attention weights.
    const float* Wv    = (const float*)d_in[4];
    const float* bv    = (const float*)d_in[5];
    const float* gamma = (const float*)d_in[8];
    const float* beta  = (const float*)d_in[9];
    const float* Wout  = (const float*)d_in[10];
    const float* bout  = (const float*)d_in[11];

    reduce_x_kernel<<<dim3(NB, ZCH), 128>>>((const float4*)x);
    gemv_fused_kernel<<<dim3(NB, KZ), ND>>>(pm, Wv, bv, gamma, beta, Wout);
    bcast_kernel<<<dim3(BGX, NB), 256>>>((const float4*)bout, (float*)d_out);
}

// round 6
// speedup vs baseline: 1.2062x; 1.2062x over previous
#include <cuda_runtime.h>

#define NB 4
#define NS 8192
#define ND 512
#define NP 32
#define NT (NP + NS)          // 8224
#define LN_EPS 1e-5f
#define ZCH 256               // chunks over S for reduce (R6: 128 -> 256)
#define CROWS (NS / ZCH)      // 32 rows per chunk
#define KZ 8                  // split-K factor for GEMVs
#define KS (ND / KZ)          // 64 k per split

// Scratch: device globals, referenced ONLY from device code.
__device__ float g_part[ZCH][NB * ND];   // per-chunk partial sums of x (2MB)
__device__ float g_vp[KZ][NB * ND];      // split-K partials of vbar
__device__ float g_yp[KZ][NB * ND];      // split-K partials of y

// ---------------------------------------------------------------------------
// K1: reduce x over S. grid (NB, ZCH)=1024 blocks, block 128. float4 loads,
// 32 rows/thread, 8 independent accumulators (MLP 8). occ ~40%.
// ---------------------------------------------------------------------------
__global__ void reduce_x_kernel(const float4* __restrict__ x4) {
    const int d4 = threadIdx.x;            // 0..127
    const int b  = blockIdx.x;
    const int z  = blockIdx.y;
    const float4* p = x4 + ((size_t)(b * NS + z * CROWS)) * (ND / 4) + d4;
    float4 a[8];
#pragma unroll
    for (int j = 0; j < 8; j++) a[j] = make_float4(0.f, 0.f, 0.f, 0.f);
#pragma unroll
    for (int i = 0; i < CROWS; i += 8) {
#pragma unroll
        for (int j = 0; j < 8; j++) {
            float4 v = p[(size_t)(i + j) * (ND / 4)];
            a[j].x += v.x; a[j].y += v.y; a[j].z += v.z; a[j].w += v.w;
        }
    }
    float4 r;
    r.x = ((a[0].x + a[1].x) + (a[2].x + a[3].x)) + ((a[4].x + a[5].x) + (a[6].x + a[7].x));
    r.y = ((a[0].y + a[1].y) + (a[2].y + a[3].y)) + ((a[4].y + a[5].y) + (a[6].y + a[7].y));
    r.z = ((a[0].z + a[1].z) + (a[2].z + a[3].z)) + ((a[4].z + a[5].z) + (a[6].z + a[7].z));
    r.w = ((a[0].w + a[1].w) + (a[2].w + a[3].w)) + ((a[4].w + a[5].w) + (a[6].w + a[7].w));
    ((float4*)g_part[z])[b * (ND / 4) + d4] = r;
}

// ---------------------------------------------------------------------------
// K2: fused cbar + split-K GEMV1 (vbar partials). grid (NB, KZ), block 512.
// ---------------------------------------------------------------------------
__global__ void gemv1_kernel(const float* __restrict__ pm,
                             const float* __restrict__ Wv) {
    const int b = blockIdx.x, z = blockIdx.y, d = threadIdx.x;
    __shared__ float sk[KS];
    if (d < KS) {
        const int kk = z * KS + d;
        float a = 0.f;
#pragma unroll 16
        for (int c = 0; c < ZCH; c++) a += g_part[c][b * ND + kk];
#pragma unroll
        for (int p = 0; p < NP; p++) a += pm[p * ND + kk];
        sk[d] = a / (float)NT;
    }
    __syncthreads();
    const float* w = Wv + (size_t)(z * KS) * ND + d;
    float acc = 0.f;
#pragma unroll
    for (int k = 0; k < KS; k++) acc += sk[k] * w[(size_t)k * ND];
    g_vp[z][b * ND + d] = acc;
}

// ---------------------------------------------------------------------------
// K3: fused vbar-combine + LayerNorm + split-K GEMV2 (y partials).
// grid (NB, KZ), block 512. LN stats recomputed redundantly per block
// (identical deterministic order in every block).
// ---------------------------------------------------------------------------
__global__ void gemv2_kernel(const float* __restrict__ bv,
                             const float* __restrict__ gamma,
                             const float* __restrict__ beta,
                             const float* __restrict__ Wout) {
    const int b = blockIdx.x, z = blockIdx.y, d = threadIdx.x;
    __shared__ float red[ND];
    __shared__ float snorm[KS];

    float vb = bv[d];
#pragma unroll
    for (int c = 0; c < KZ; c++) vb += g_vp[c][b * ND + d];

    red[d] = vb;
    __syncthreads();
    for (int s = ND / 2; s > 0; s >>= 1) {
        if (d < s) red[d] += red[d + s];
        __syncthreads();
    }
    const float mu = red[0] / (float)ND;
    __syncthreads();
    const float diff = vb - mu;
    red[d] = diff * diff;
    __syncthreads();
    for (int s = ND / 2; s > 0; s >>= 1) {
        if (d < s) red[d] += red[d + s];
        __syncthreads();
    }
    const float inv = rsqrtf(red[0] / (float)ND + LN_EPS);
    const float nrm = diff * inv * gamma[d] + beta[d];
    if (d >= z * KS && d < (z + 1) * KS) snorm[d - z * KS] = nrm;
    __syncthreads();

    const float* w = Wout + (size_t)(z * KS) * ND + d;
    float acc = 0.f;
#pragma unroll
    for (int k = 0; k < KS; k++) acc += snorm[k] * w[(size_t)k * ND];
    g_yp[z][b * ND + d] = acc;
}

// ---------------------------------------------------------------------------
// K4: combine y partials + bout, broadcast row to all T positions.
// grid (296, NB), block 256. Per-thread row value is loop-invariant
// (stride multiple of 128) -> register; loop is pure STG.128.
// ---------------------------------------------------------------------------
#define BGX 296
__global__ void bcast_kernel(const float4* __restrict__ bout4,
                             float* __restrict__ out) {
    const int b = blockIdx.y;
    const int tid = threadIdx.x;
    __shared__ float4 sy[ND / 4];
    if (tid < ND / 4) {
        float4 a = bout4[tid];
#pragma unroll
        for (int z = 0; z < KZ; z++) {
            float4 v = ((const float4*)g_yp[z])[b * (ND / 4) + tid];
            a.x += v.x; a.y += v.y; a.z += v.z; a.w += v.w;
        }
        sy[tid] = a;
    }
    __syncthreads();

    const size_t start  = (size_t)blockIdx.x * blockDim.x + tid;
    const float4 val    = sy[start & (ND / 4 - 1)];   // constant per thread
    float4* o = (float4*)out + (size_t)b * NT * (ND / 4);
    const size_t n4     = (size_t)NT * (ND / 4);      // 1,052,672
    const size_t stride = (size_t)BGX * 256;          // multiple of 128
#pragma unroll 4
    for (size_t i = start; i < n4; i += stride)
        o[i] = val;
}

// ---------------------------------------------------------------------------
extern "C" void kernel_launch(void* const* d_in, const int* in_sizes, int n_in,
                              void* d_out, int out_size) {
    const float* x     = (const float*)d_in[0];
    const float* pm    = (const float*)d_in[1];
    // d_in[2]=Wk, [3]=bk, [6]=Wq, [7]=bq unused: softmax over zero-state and
    // constant-in-m logits collapse to uniform attention weights.
    const float* Wv    = (const float*)d_in[4];
    const float* bv    = (const float*)d_in[5];
    const float* gamma = (const float*)d_in[8];
    const float* beta  = (const float*)d_in[9];
    const float* Wout  = (const float*)d_in[10];
    const float* bout  = (const float*)d_in[11];

    reduce_x_kernel<<<dim3(NB, ZCH), 128>>>((const float4*)x);
    gemv1_kernel<<<dim3(NB, KZ), ND>>>(pm, Wv);
    gemv2_kernel<<<dim3(NB, KZ), ND>>>(bv, gamma, beta, Wout);
    bcast_kernel<<<dim3(BGX, NB), 256>>>((const float4*)bout, (float*)d_out);
}

// round 7
// speedup vs baseline: 1.3684x; 1.1345x over previous
#include <cuda_runtime.h>

#define NB 4
#define NS 8192
#define ND 512
#define NP 32
#define NT (NP + NS)          // 8224
#define LN_EPS 1e-5f
#define ZCH 128               // chunks over S for reduce (R4-proven)
#define CROWS (NS / ZCH)      // 64 rows per chunk
#define KZ 8                  // split-K factor for GEMVs
#define KS (ND / KZ)          // 64 k per split

// Scratch: device globals, referenced ONLY from device code.
__device__ float g_part[ZCH][NB * ND];   // per-chunk partial sums of x
__device__ float g_vp[KZ][NB * ND];      // split-K partials of vbar
__device__ float g_yp[KZ][NB * ND];      // split-K partials of y

// ---------------------------------------------------------------------------
// K1: reduce x over S. grid (NB, ZCH), block 128. float4 loads, 64 rows/thr,
// 8 independent accumulators (R4-proven, at its BW floor ~4.1 TB/s).
// ---------------------------------------------------------------------------
__global__ void reduce_x_kernel(const float4* __restrict__ x4) {
    const int d4 = threadIdx.x;            // 0..127
    const int b  = blockIdx.x;
    const int z  = blockIdx.y;
    const float4* p = x4 + ((size_t)(b * NS + z * CROWS)) * (ND / 4) + d4;
    float4 a[8];
#pragma unroll
    for (int j = 0; j < 8; j++) a[j] = make_float4(0.f, 0.f, 0.f, 0.f);
#pragma unroll
    for (int i = 0; i < CROWS; i += 8) {
#pragma unroll
        for (int j = 0; j < 8; j++) {
            float4 v = p[(size_t)(i + j) * (ND / 4)];
            a[j].x += v.x; a[j].y += v.y; a[j].z += v.z; a[j].w += v.w;
        }
    }
    float4 r;
    r.x = ((a[0].x + a[1].x) + (a[2].x + a[3].x)) + ((a[4].x + a[5].x) + (a[6].x + a[7].x));
    r.y = ((a[0].y + a[1].y) + (a[2].y + a[3].y)) + ((a[4].y + a[5].y) + (a[6].y + a[7].y));
    r.z = ((a[0].z + a[1].z) + (a[2].z + a[3].z)) + ((a[4].z + a[5].z) + (a[6].z + a[7].z));
    r.w = ((a[0].w + a[1].w) + (a[2].w + a[3].w)) + ((a[4].w + a[5].w) + (a[6].w + a[7].w));
    ((float4*)g_part[z])[b * (ND / 4) + d4] = r;
}

// ---------------------------------------------------------------------------
// K2: fused cbar + split-K GEMV1 (vbar partials). grid (NB, KZ), block 512.
// ---------------------------------------------------------------------------
__global__ void gemv1_kernel(const float* __restrict__ pm,
                             const float* __restrict__ Wv) {
    const int b = blockIdx.x, z = blockIdx.y, d = threadIdx.x;
    __shared__ float sk[KS];
    if (d < KS) {
        const int kk = z * KS + d;
        float a = 0.f;
#pragma unroll 16
        for (int c = 0; c < ZCH; c++) a += g_part[c][b * ND + kk];
#pragma unroll
        for (int p = 0; p < NP; p++) a += pm[p * ND + kk];
        sk[d] = a / (float)NT;
    }
    __syncthreads();
    const float* w = Wv + (size_t)(z * KS) * ND + d;
    float acc = 0.f;
#pragma unroll
    for (int k = 0; k < KS; k++) acc += sk[k] * w[(size_t)k * ND];
    g_vp[z][b * ND + d] = acc;
}

// ---------------------------------------------------------------------------
// K3: fused vbar-combine + LayerNorm + split-K GEMV2 (y partials).
// grid (NB, KZ), block 512.
// ---------------------------------------------------------------------------
__global__ void gemv2_kernel(const float* __restrict__ bv,
                             const float* __restrict__ gamma,
                             const float* __restrict__ beta,
                             const float* __restrict__ Wout) {
    const int b = blockIdx.x, z = blockIdx.y, d = threadIdx.x;
    __shared__ float red[ND];
    __shared__ float snorm[KS];

    float vb = bv[d];
#pragma unroll
    for (int c = 0; c < KZ; c++) vb += g_vp[c][b * ND + d];

    red[d] = vb;
    __syncthreads();
    for (int s = ND / 2; s > 0; s >>= 1) {
        if (d < s) red[d] += red[d + s];
        __syncthreads();
    }
    const float mu = red[0] / (float)ND;
    __syncthreads();
    const float diff = vb - mu;
    red[d] = diff * diff;
    __syncthreads();
    for (int s = ND / 2; s > 0; s >>= 1) {
        if (d < s) red[d] += red[d + s];
        __syncthreads();
    }
    const float inv = rsqrtf(red[0] / (float)ND + LN_EPS);
    const float nrm = diff * inv * gamma[d] + beta[d];
    if (d >= z * KS && d < (z + 1) * KS) snorm[d - z * KS] = nrm;
    __syncthreads();

    const float* w = Wout + (size_t)(z * KS) * ND + d;
    float acc = 0.f;
#pragma unroll
    for (int k = 0; k < KS; k++) acc += snorm[k] * w[(size_t)k * ND];
    g_yp[z][b * ND + d] = acc;
}

// ---------------------------------------------------------------------------
// K4: combine y partials + bout, broadcast. grid (257, NB), block 256.
// NT = 8224 = 257 * 32 -> each block owns 32 CONTIGUOUS rows (64KB).
// Per-thread value is loop-invariant (stride 256 ≡ 0 mod 128). Streaming
// stores (evict-first): write-once data shouldn't own L2.
// ---------------------------------------------------------------------------
#define BROWS 32
#define BGX (NT / BROWS)      // 257
__global__ void bcast_kernel(const float4* __restrict__ bout4,
                             float* __restrict__ out) {
    const int b = blockIdx.y;
    const int tid = threadIdx.x;
    __shared__ float4 sy[ND / 4];
    if (tid < ND / 4) {
        float4 a = bout4[tid];
#pragma unroll
        for (int z = 0; z < KZ; z++) {
            float4 v = ((const float4*)g_yp[z])[b * (ND / 4) + tid];
            a.x += v.x; a.y += v.y; a.z += v.z; a.w += v.w;
        }
        sy[tid] = a;
    }
    __syncthreads();

    // Block's contiguous chunk: BROWS rows = BROWS*128 float4s.
    const size_t chunk0 = (size_t)blockIdx.x * (BROWS * (ND / 4));
    const float4 val = sy[(chunk0 + tid) & (ND / 4 - 1)];  // invariant per thread
    float4* o = (float4*)out + (size_t)b * NT * (ND / 4) + chunk0 + tid;
#pragma unroll
    for (int j = 0; j < BROWS * (ND / 4) / 256; j++) {     // 16 iterations
        asm volatile("st.global.cs.v4.f32 [%0], {%1, %2, %3, %4};"
                     :: "l"(o + (size_t)j * 256),
                        "f"(val.x), "f"(val.y), "f"(val.z), "f"(val.w)
                     : "memory");
    }
}

// ---------------------------------------------------------------------------
extern "C" void kernel_launch(void* const* d_in, const int* in_sizes, int n_in,
                              void* d_out, int out_size) {
    const float* x     = (const float*)d_in[0];
    const float* pm    = (const float*)d_in[1];
    // d_in[2]=Wk, [3]=bk, [6]=Wq, [7]=bq unused: softmax over zero-state and
    // constant-in-m logits collapse to uniform attention weights.
    const float* Wv    = (const float*)d_in[4];
    const float* bv    = (const float*)d_in[5];
    const float* gamma = (const float*)d_in[8];
    const float* beta  = (const float*)d_in[9];
    const float* Wout  = (const float*)d_in[10];
    const float* bout  = (const float*)d_in[11];

    reduce_x_kernel<<<dim3(NB, ZCH), 128>>>((const float4*)x);
    gemv1_kernel<<<dim3(NB, KZ), ND>>>(pm, Wv);
    gemv2_kernel<<<dim3(NB, KZ), ND>>>(bv, gamma, beta, Wout);
    bcast_kernel<<<dim3(BGX, NB), 256>>>((const float4*)bout, (float*)d_out);
}